// round 11
// baseline (speedup 1.0000x reference)
#include <cuda_runtime.h>
#include <cuda_fp16.h>
#include <cstdint>

// GCNConv: out = D^-1/2 (A + I) D^-1/2 (x @ W) + b
// R11 = R10 with ONE change: aggregate v2 -- warp-shuffle index staging
//       (no per-edge csrc load chain) + 8-deep MLP on fp16 row gathers.

#define MAX_N 100000
#define MAX_E 1600000
#define C 128
#define SCAN_B 512
#define NB_MAX ((MAX_N + SCAN_B - 1) / SCAN_B)

#define GM 64          // rows per tile
#define SA 132         // x smem row stride (words)
#define SBW 264        // W pair-row stride (words); 264%32==8 -> conflict-free
#define GEMM_GRID_MAX 296

__device__ int    g_deg[MAX_N];
__device__ float  g_dinv[MAX_N];
__device__ int    g_rowptr[MAX_N + 1];
__device__ int    g_cursor[MAX_N];
__device__ int    g_csrc[MAX_E];
__device__ unsigned long long g_status[NB_MAX];
__device__ int    g_ticket;
__device__ float  g_wf[64 * SBW];                  // tf32 W, pair-permuted rows
__device__ __half g_hh[(size_t)MAX_N * C];         // h' = (xW)*dinv, fp16, L2-resident

__device__ __forceinline__ uint32_t f2tf32(float f) {
    uint32_t u;
    asm("cvt.rna.tf32.f32 %0, %1;" : "=r"(u) : "f"(f));
    return u;
}
__device__ __forceinline__ float tf32f(float f) { return __uint_as_float(f2tf32(f)); }

// int64 payload (values < 2^31) has zero high words at odd int32 slots.
__device__ __forceinline__ int detect_is64(const int* __restrict__ ei32) {
    __shared__ int s64;
    if (threadIdx.x == 0) s64 = 1;
    __syncthreads();
    if (threadIdx.x < 256 && ei32[2 * threadIdx.x + 1] != 0) s64 = 0;
    __syncthreads();
    return s64;
}

// ---------------------------------------------------------------------------
// count_deg: in-degree + zero scan aux + rowptr[n]=E + (block 1) tf32-permute W.
// ---------------------------------------------------------------------------
__global__ __launch_bounds__(256) void count_deg(const int* __restrict__ ei32,
                                                 const float* __restrict__ W,
                                                 int E, int n, int NB) {
    int is64 = detect_is64(ei32);
    if (blockIdx.x == 0) {
        if (threadIdx.x == 0) { g_ticket = 0; g_rowptr[n] = E; }
        for (int p = threadIdx.x; p < NB; p += 256) g_status[p] = 0ULL;
    }
    int wblk = (gridDim.x > 1) ? 1 : 0;
    if (blockIdx.x == wblk) {
        for (int idx = threadIdx.x; idx < 64 * 128; idx += 256) {
            int p = idx >> 7, c = idx & 127;
            int k8 = p >> 2, t = p & 3;
            g_wf[p * SBW + 2 * c]     = tf32f(W[(size_t)(k8 * 8 + t) * C + c]);
            g_wf[p * SBW + 2 * c + 1] = tf32f(W[(size_t)(k8 * 8 + t + 4) * C + c]);
        }
    }
    int e0 = (blockIdx.x * 256 + threadIdx.x) * 4;
    if (e0 >= E) return;
    int m = E - e0; if (m > 4) m = 4;
    if (is64) {
        const long long* d = (const long long*)ei32 + (size_t)E + e0;
#pragma unroll
        for (int k = 0; k < 4; k++)
            if (k < m) atomicAdd(&g_deg[(int)d[k]], 1);
    } else {
        const int* d = ei32 + (size_t)E + e0;
#pragma unroll
        for (int k = 0; k < 4; k++)
            if (k < m) atomicAdd(&g_deg[d[k]], 1);
    }
}

// ---------------------------------------------------------------------------
// Single-pass exclusive scan (decoupled lookback, ticket-ordered) + dinv.
// ---------------------------------------------------------------------------
__global__ __launch_bounds__(SCAN_B) void scan_csr(int n) {
    __shared__ int sh[SCAN_B];
    __shared__ int s_ticket, s_prefix;
    if (threadIdx.x == 0) s_ticket = atomicAdd(&g_ticket, 1);
    __syncthreads();
    const int t = s_ticket;
    const int i = t * SCAN_B + threadIdx.x;

    int cnt = (i < n) ? g_deg[i] : 0;
    if (i < n) g_dinv[i] = rsqrtf((float)(cnt + 1));

    sh[threadIdx.x] = cnt;
    __syncthreads();
    for (int off = 1; off < SCAN_B; off <<= 1) {
        int v = (threadIdx.x >= off) ? sh[threadIdx.x - off] : 0;
        __syncthreads();
        sh[threadIdx.x] += v;
        __syncthreads();
    }
    int incl  = sh[threadIdx.x];
    int total = sh[SCAN_B - 1];

    if (threadIdx.x < 32) {
        int lane = threadIdx.x;
        if (lane == 0) {
            if (t == 0) {
                atomicExch(&g_status[0], (2ULL << 62) | (unsigned)total);
                s_prefix = 0;
            } else {
                atomicExch(&g_status[t], (1ULL << 62) | (unsigned)total);
            }
        }
        if (t > 0) {
            long long pref = 0;
            int base = t;
            for (;;) {
                int p = base - 1 - lane;
                int flag = 0, val = 0;
                if (p >= 0) {
                    unsigned long long s;
                    do {
                        s = atomicAdd(&g_status[p], 0ULL);
                        flag = (int)(s >> 62);
                    } while (flag == 0);
                    val = (int)(s & 0xffffffffu);
                }
                unsigned f2 = __ballot_sync(0xffffffffu, p >= 0 && flag == 2);
                int first = f2 ? (__ffs(f2) - 1) : 32;
                int contrib = (p >= 0 && lane <= first) ? val : 0;
#pragma unroll
                for (int off = 16; off; off >>= 1)
                    contrib += __shfl_down_sync(0xffffffffu, contrib, off);
                if (lane == 0) pref += contrib;
                if (f2) break;
                base -= 32;
            }
            if (lane == 0) {
                atomicExch(&g_status[t], (2ULL << 62) | (unsigned)(pref + (long long)total));
                s_prefix = (int)pref;
            }
        }
    }
    __syncthreads();
    if (i < n) {
        int excl = s_prefix + incl - cnt;
        g_rowptr[i] = excl;
        g_cursor[i] = excl;
    }
}

// ---------------------------------------------------------------------------
// Fill CSR: csrc[pos] = src grouped by dst. 4 edges per thread.
// ---------------------------------------------------------------------------
__global__ __launch_bounds__(256) void fill_csr(const int* __restrict__ ei32, int E) {
    int is64 = detect_is64(ei32);
    int e0 = (blockIdx.x * 256 + threadIdx.x) * 4;
    if (e0 >= E) return;
    int m = E - e0; if (m > 4) m = 4;
#pragma unroll
    for (int k = 0; k < 4; k++) {
        if (k >= m) break;
        int e = e0 + k;
        int src, dst;
        if (is64) {
            src = (int)((const long long*)ei32)[e];
            dst = (int)((const long long*)ei32)[(size_t)E + e];
        } else {
            src = ei32[e];
            dst = ei32[(size_t)E + e];
        }
        int p = atomicAdd(&g_cursor[dst], 1);
        g_csrc[p] = src;
    }
}

// ---------------------------------------------------------------------------
// Persistent TF32 GEMM: h'[r] = (x@W)[r] * dinv[r], stored fp16. (As R10.)
// ---------------------------------------------------------------------------
__global__ __launch_bounds__(256, 2) void gemm_tf32(const float* __restrict__ x,
                                                    int n, int ntiles) {
    extern __shared__ float smem[];
    float* xs = smem;              // [GM][SA]
    float* ws = smem + GM * SA;    // [64][SBW] pair-rows

    const int tid  = threadIdx.x;
    const int lane = tid & 31;
    const int wid  = tid >> 5;
    const int wm   = wid >> 2;
    const int wn   = wid & 3;
    const int g    = lane >> 2;
    const int t    = lane & 3;
    const int lr   = tid >> 2;
    const int lq   = tid & 3;

    {
        const float4* wsrc = (const float4*)g_wf;
        float4* wdst = (float4*)ws;
        for (int i = tid; i < 64 * SBW / 4; i += 256) wdst[i] = wsrc[i];
    }

    float4 xr[8];
    int tile = blockIdx.x;
    if (tile < ntiles) {
        int grow = tile * GM + lr;
        const float* xp = x + (size_t)grow * C;
#pragma unroll
        for (int i = 0; i < 8; i++)
            xr[i] = (grow < n) ? *(const float4*)(xp + (lq * 8 + i) * 4)
                               : make_float4(0.f, 0.f, 0.f, 0.f);
    }

    for (; tile < ntiles; tile += gridDim.x) {
        __syncthreads();
        {
            float* sp = xs + lr * SA;
#pragma unroll
            for (int i = 0; i < 8; i++) {
                float4 v = xr[i];
                v.x = tf32f(v.x); v.y = tf32f(v.y);
                v.z = tf32f(v.z); v.w = tf32f(v.w);
                *(float4*)(sp + (lq * 8 + i) * 4) = v;
            }
        }
        __syncthreads();

        int next = tile + gridDim.x;
        if (next < ntiles) {
            int grow = next * GM + lr;
            const float* xp = x + (size_t)grow * C;
#pragma unroll
            for (int i = 0; i < 8; i++)
                xr[i] = (grow < n) ? *(const float4*)(xp + (lq * 8 + i) * 4)
                                   : make_float4(0.f, 0.f, 0.f, 0.f);
        }

        float acc[2][4][4];
#pragma unroll
        for (int ms = 0; ms < 2; ms++)
#pragma unroll
            for (int ns = 0; ns < 4; ns++)
#pragma unroll
                for (int j = 0; j < 4; j++) acc[ms][ns][j] = 0.f;

#pragma unroll
        for (int k = 0; k < 16; k++) {
            uint32_t a[2][4];
#pragma unroll
            for (int ms = 0; ms < 2; ms++) {
                const float* base = xs + (wm * 32 + ms * 16) * SA + k * 8;
                a[ms][0] = __float_as_uint(base[g * SA + t]);
                a[ms][1] = __float_as_uint(base[(g + 8) * SA + t]);
                a[ms][2] = __float_as_uint(base[g * SA + t + 4]);
                a[ms][3] = __float_as_uint(base[(g + 8) * SA + t + 4]);
            }
#pragma unroll
            for (int ns = 0; ns < 4; ns++) {
                float2 bv = *(const float2*)(ws + (k * 4 + t) * SBW
                                             + 2 * (wn * 32 + ns * 8 + g));
                uint32_t b0 = __float_as_uint(bv.x);
                uint32_t b1 = __float_as_uint(bv.y);
#pragma unroll
                for (int ms = 0; ms < 2; ms++) {
                    asm volatile(
                        "mma.sync.aligned.m16n8k8.row.col.f32.tf32.tf32.f32 "
                        "{%0,%1,%2,%3}, {%4,%5,%6,%7}, {%8,%9}, {%0,%1,%2,%3};"
                        : "+f"(acc[ms][ns][0]), "+f"(acc[ms][ns][1]),
                          "+f"(acc[ms][ns][2]), "+f"(acc[ms][ns][3])
                        : "r"(a[ms][0]), "r"(a[ms][1]), "r"(a[ms][2]), "r"(a[ms][3]),
                          "r"(b0), "r"(b1));
                }
            }
        }

        int row0 = tile * GM;
#pragma unroll
        for (int ms = 0; ms < 2; ms++) {
            int r = row0 + wm * 32 + ms * 16 + g;
            float s0 = (r < n)     ? g_dinv[r]     : 0.f;
            float s1 = (r + 8 < n) ? g_dinv[r + 8] : 0.f;
#pragma unroll
            for (int ns = 0; ns < 4; ns++) {
                int c = wn * 32 + ns * 8 + t * 2;
                if (r < n)
                    *(__half2*)(g_hh + (size_t)r * C + c) =
                        __floats2half2_rn(acc[ms][ns][0] * s0, acc[ms][ns][1] * s0);
                if (r + 8 < n)
                    *(__half2*)(g_hh + (size_t)(r + 8) * C + c) =
                        __floats2half2_rn(acc[ms][ns][2] * s1, acc[ms][ns][3] * s1);
            }
        }
    }
}

// ---------------------------------------------------------------------------
// Aggregate v2: one warp per dst node.
//   - indices staged warp-wide: one coalesced LDG fetches 32 csrc, broadcast
//     via shfl -> no per-edge index load chain.
//   - 8-deep unroll on fp16 row gathers (MLP=8), fp32 accumulation.
// ---------------------------------------------------------------------------
__device__ __forceinline__ void acc_row(float4& a, uint2 v) {
    float2 lo = __half22float2(*(__half2*)&v.x);
    float2 hi = __half22float2(*(__half2*)&v.y);
    a.x += lo.x; a.y += lo.y; a.z += hi.x; a.w += hi.y;
}

__global__ __launch_bounds__(256) void aggregate(const float* __restrict__ b,
                                                 float* __restrict__ out, int n) {
    int w    = (blockIdx.x * blockDim.x + threadIdx.x) >> 5;
    int lane = threadIdx.x & 31;
    if (w >= n) return;

    float di = g_dinv[w];
    int j0 = g_rowptr[w];
    int j1 = g_rowptr[w + 1];
    if (lane == 0) g_deg[w] = 0;      // reset counts for next call

    const uint2* hbase = (const uint2*)g_hh;   // row r, lane l -> hbase[r*32+l]
    float4 a0 = make_float4(0.f, 0.f, 0.f, 0.f);
    float4 a1 = make_float4(0.f, 0.f, 0.f, 0.f);
    float4 a2 = make_float4(0.f, 0.f, 0.f, 0.f);
    float4 a3 = make_float4(0.f, 0.f, 0.f, 0.f);
    acc_row(a0, hbase[(size_t)w * 32 + lane]);   // self loop

    for (int base = j0; base < j1; base += 32) {
        int m = j1 - base; if (m > 32) m = 32;
        int myidx = (base + lane < j1) ? g_csrc[base + lane] : 0;

        int k = 0;
        for (; k + 8 <= m; k += 8) {
            int s0 = __shfl_sync(0xffffffffu, myidx, k + 0);
            int s1 = __shfl_sync(0xffffffffu, myidx, k + 1);
            int s2 = __shfl_sync(0xffffffffu, myidx, k + 2);
            int s3 = __shfl_sync(0xffffffffu, myidx, k + 3);
            int s4 = __shfl_sync(0xffffffffu, myidx, k + 4);
            int s5 = __shfl_sync(0xffffffffu, myidx, k + 5);
            int s6 = __shfl_sync(0xffffffffu, myidx, k + 6);
            int s7 = __shfl_sync(0xffffffffu, myidx, k + 7);
            uint2 v0 = hbase[(size_t)s0 * 32 + lane];
            uint2 v1 = hbase[(size_t)s1 * 32 + lane];
            uint2 v2 = hbase[(size_t)s2 * 32 + lane];
            uint2 v3 = hbase[(size_t)s3 * 32 + lane];
            uint2 v4 = hbase[(size_t)s4 * 32 + lane];
            uint2 v5 = hbase[(size_t)s5 * 32 + lane];
            uint2 v6 = hbase[(size_t)s6 * 32 + lane];
            uint2 v7 = hbase[(size_t)s7 * 32 + lane];
            acc_row(a0, v0); acc_row(a1, v1); acc_row(a2, v2); acc_row(a3, v3);
            acc_row(a0, v4); acc_row(a1, v5); acc_row(a2, v6); acc_row(a3, v7);
        }
        for (; k + 2 <= m; k += 2) {
            int s0 = __shfl_sync(0xffffffffu, myidx, k);
            int s1 = __shfl_sync(0xffffffffu, myidx, k + 1);
            uint2 v0 = hbase[(size_t)s0 * 32 + lane];
            uint2 v1 = hbase[(size_t)s1 * 32 + lane];
            acc_row(a0, v0); acc_row(a1, v1);
        }
        for (; k < m; k++) {
            int s0 = __shfl_sync(0xffffffffu, myidx, k);
            acc_row(a0, hbase[(size_t)s0 * 32 + lane]);
        }
    }

    float4 bv = *(const float4*)(b + lane * 4);
    float4 o;
    o.x = fmaf(di, a0.x + a1.x + a2.x + a3.x, bv.x);
    o.y = fmaf(di, a0.y + a1.y + a2.y + a3.y, bv.y);
    o.z = fmaf(di, a0.z + a1.z + a2.z + a3.z, bv.z);
    o.w = fmaf(di, a0.w + a1.w + a2.w + a3.w, bv.w);
    *(float4*)(out + (size_t)w * C + lane * 4) = o;
}

// ---------------------------------------------------------------------------
extern "C" void kernel_launch(void* const* d_in, const int* in_sizes, int n_in,
                              void* d_out, int out_size) {
    const float* x  = (const float*)d_in[0];
    const int*   ei = (const int*)d_in[1];
    const float* W  = (const float*)d_in[2];
    const float* b  = (const float*)d_in[3];
    float* out = (float*)d_out;

    int n  = in_sizes[0] / C;
    int E  = in_sizes[1] / 2;
    int NB = (n + SCAN_B - 1) / SCAN_B;
    int EB = (E + 1023) / 1024;
    int ntiles = (n + GM - 1) / GM;
    int ggrid = ntiles < GEMM_GRID_MAX ? ntiles : GEMM_GRID_MAX;

    const int GEMM_SMEM = (GM * SA + 64 * SBW) * (int)sizeof(float);  // 101376 B
    cudaFuncSetAttribute(gemm_tf32, cudaFuncAttributeMaxDynamicSharedMemorySize,
                         GEMM_SMEM);

    count_deg<<<EB, 256>>>(ei, W, E, n, NB);
    scan_csr<<<NB, SCAN_B>>>(n);
    fill_csr<<<EB, 256>>>(ei, E);
    gemm_tf32<<<ggrid, 256, GEMM_SMEM>>>(x, n, ntiles);
    aggregate<<<(n * 32 + 255) / 256, 256>>>(b, out, n);
}

// round 12
// speedup vs baseline: 1.0870x; 1.0870x over previous
#include <cuda_runtime.h>
#include <cuda_fp16.h>
#include <cstdint>

// GCNConv: out = D^-1/2 (A + I) D^-1/2 (x @ W) + b
// R12 = R10 with the GEMM moved from tf32 (m16n8k8, 101KB smem, 2 blk/SM)
//       to fp16 (m16n8k16, 52KB smem, 4 blk/SM). Same 10-bit mantissa ->
//       precision unchanged. Aggregate = R10 (known good).

#define MAX_N 100000
#define MAX_E 1600000
#define C 128
#define SCAN_B 512
#define NB_MAX ((MAX_N + SCAN_B - 1) / SCAN_B)

#define GM 64           // rows per GEMM tile
#define SXH 136         // xs row stride (halves)
#define SWH 136         // Wt row stride (halves)
#define GEMM_GRID_MAX 592

__device__ int    g_deg[MAX_N];
__device__ float  g_dinv[MAX_N];
__device__ int    g_rowptr[MAX_N + 1];
__device__ int    g_cursor[MAX_N];
__device__ int    g_csrc[MAX_E];
__device__ unsigned long long g_status[NB_MAX];
__device__ int    g_ticket;
__device__ __align__(16) __half g_wh[128 * SWH];   // Wt[n][k] fp16
__device__ __half g_hh[(size_t)MAX_N * C];         // h' = (xW)*dinv, fp16

// int64 payload (values < 2^31) has zero high words at odd int32 slots.
__device__ __forceinline__ int detect_is64(const int* __restrict__ ei32) {
    __shared__ int s64;
    if (threadIdx.x == 0) s64 = 1;
    __syncthreads();
    if (threadIdx.x < 256 && ei32[2 * threadIdx.x + 1] != 0) s64 = 0;
    __syncthreads();
    return s64;
}

// ---------------------------------------------------------------------------
// count_deg: in-degree + zero scan aux + rowptr[n]=E + (block 1) fp16 W^T.
// ---------------------------------------------------------------------------
__global__ __launch_bounds__(256) void count_deg(const int* __restrict__ ei32,
                                                 const float* __restrict__ W,
                                                 int E, int n, int NB) {
    int is64 = detect_is64(ei32);
    if (blockIdx.x == 0) {
        if (threadIdx.x == 0) { g_ticket = 0; g_rowptr[n] = E; }
        for (int p = threadIdx.x; p < NB; p += 256) g_status[p] = 0ULL;
    }
    int wblk = (gridDim.x > 1) ? 1 : 0;
    if (blockIdx.x == wblk) {
        // Wt[nn][k] = W[k][nn]; coalesced reads over nn.
        for (int idx = threadIdx.x; idx < 128 * 128; idx += 256) {
            int k = idx >> 7, nn = idx & 127;
            g_wh[nn * SWH + k] = __float2half_rn(W[(size_t)k * C + nn]);
        }
    }
    int e0 = (blockIdx.x * 256 + threadIdx.x) * 4;
    if (e0 >= E) return;
    int m = E - e0; if (m > 4) m = 4;
    if (is64) {
        const long long* d = (const long long*)ei32 + (size_t)E + e0;
#pragma unroll
        for (int k = 0; k < 4; k++)
            if (k < m) atomicAdd(&g_deg[(int)d[k]], 1);
    } else {
        const int* d = ei32 + (size_t)E + e0;
#pragma unroll
        for (int k = 0; k < 4; k++)
            if (k < m) atomicAdd(&g_deg[d[k]], 1);
    }
}

// ---------------------------------------------------------------------------
// Single-pass exclusive scan (decoupled lookback, ticket-ordered) + dinv.
// ---------------------------------------------------------------------------
__global__ __launch_bounds__(SCAN_B) void scan_csr(int n) {
    __shared__ int sh[SCAN_B];
    __shared__ int s_ticket, s_prefix;
    if (threadIdx.x == 0) s_ticket = atomicAdd(&g_ticket, 1);
    __syncthreads();
    const int t = s_ticket;
    const int i = t * SCAN_B + threadIdx.x;

    int cnt = (i < n) ? g_deg[i] : 0;
    if (i < n) g_dinv[i] = rsqrtf((float)(cnt + 1));

    sh[threadIdx.x] = cnt;
    __syncthreads();
    for (int off = 1; off < SCAN_B; off <<= 1) {
        int v = (threadIdx.x >= off) ? sh[threadIdx.x - off] : 0;
        __syncthreads();
        sh[threadIdx.x] += v;
        __syncthreads();
    }
    int incl  = sh[threadIdx.x];
    int total = sh[SCAN_B - 1];

    if (threadIdx.x < 32) {
        int lane = threadIdx.x;
        if (lane == 0) {
            if (t == 0) {
                atomicExch(&g_status[0], (2ULL << 62) | (unsigned)total);
                s_prefix = 0;
            } else {
                atomicExch(&g_status[t], (1ULL << 62) | (unsigned)total);
            }
        }
        if (t > 0) {
            long long pref = 0;
            int base = t;
            for (;;) {
                int p = base - 1 - lane;
                int flag = 0, val = 0;
                if (p >= 0) {
                    unsigned long long s;
                    do {
                        s = atomicAdd(&g_status[p], 0ULL);
                        flag = (int)(s >> 62);
                    } while (flag == 0);
                    val = (int)(s & 0xffffffffu);
                }
                unsigned f2 = __ballot_sync(0xffffffffu, p >= 0 && flag == 2);
                int first = f2 ? (__ffs(f2) - 1) : 32;
                int contrib = (p >= 0 && lane <= first) ? val : 0;
#pragma unroll
                for (int off = 16; off; off >>= 1)
                    contrib += __shfl_down_sync(0xffffffffu, contrib, off);
                if (lane == 0) pref += contrib;
                if (f2) break;
                base -= 32;
            }
            if (lane == 0) {
                atomicExch(&g_status[t], (2ULL << 62) | (unsigned)(pref + (long long)total));
                s_prefix = (int)pref;
            }
        }
    }
    __syncthreads();
    if (i < n) {
        int excl = s_prefix + incl - cnt;
        g_rowptr[i] = excl;
        g_cursor[i] = excl;
    }
}

// ---------------------------------------------------------------------------
// Fill CSR: csrc[pos] = src grouped by dst. 4 edges per thread.
// ---------------------------------------------------------------------------
__global__ __launch_bounds__(256) void fill_csr(const int* __restrict__ ei32, int E) {
    int is64 = detect_is64(ei32);
    int e0 = (blockIdx.x * 256 + threadIdx.x) * 4;
    if (e0 >= E) return;
    int m = E - e0; if (m > 4) m = 4;
#pragma unroll
    for (int k = 0; k < 4; k++) {
        if (k >= m) break;
        int e = e0 + k;
        int src, dst;
        if (is64) {
            src = (int)((const long long*)ei32)[e];
            dst = (int)((const long long*)ei32)[(size_t)E + e];
        } else {
            src = ei32[e];
            dst = ei32[(size_t)E + e];
        }
        int p = atomicAdd(&g_cursor[dst], 1);
        g_csrc[p] = src;
    }
}

// ---------------------------------------------------------------------------
// Persistent fp16 GEMM (m16n8k16, fp32 accum): h'[r] = (x@W)[r]*dinv[r], fp16 out.
// smem: xs 64x136 halves (17.4KB) + Wt 128x136 halves (34.8KB) = 52KB -> 4 blk/SM.
// A frags: ldmatrix.x4.b16 (conflict-free: 272B row stride = 4-bank shift).
// B frags: 2x LDS.32, bank = 4g+t bijective -> conflict-free.
// ---------------------------------------------------------------------------
__global__ __launch_bounds__(256, 4) void gemm_fp16(const float* __restrict__ x,
                                                    int n, int ntiles) {
    extern __shared__ __half smemh[];
    __half* xs = smemh;                 // [GM][SXH]
    __half* ws = smemh + GM * SXH;      // [128][SWH]

    const int tid  = threadIdx.x;
    const int lane = tid & 31;
    const int wid  = tid >> 5;
    const int wm   = wid >> 2;          // 0..1
    const int wn   = wid & 3;           // 0..3
    const int g    = lane >> 2;         // 0..7
    const int t    = lane & 3;          // 0..3
    const int lr   = tid >> 2;          // load row 0..63
    const int lq   = tid & 3;           // load quarter

    {   // copy fp16 Wt into smem once per block (16B chunks)
        const uint4* wsrc = (const uint4*)g_wh;
        uint4* wdst = (uint4*)ws;
        for (int i = tid; i < 128 * SWH / 8; i += 256) wdst[i] = wsrc[i];
    }

    // prefetch first tile
    float4 xr[8];
    int tile = blockIdx.x;
    if (tile < ntiles) {
        int grow = tile * GM + lr;
        const float* xp = x + (size_t)grow * C;
#pragma unroll
        for (int i = 0; i < 8; i++)
            xr[i] = (grow < n) ? *(const float4*)(xp + (lq * 8 + i) * 4)
                               : make_float4(0.f, 0.f, 0.f, 0.f);
    }

    const uint32_t xs_u32 = (uint32_t)__cvta_generic_to_shared(xs);
    uint32_t addrA[2];
#pragma unroll
    for (int ms = 0; ms < 2; ms++)
        addrA[ms] = xs_u32 +
            (((wm * 32 + ms * 16 + (lane & 15)) * SXH) + ((lane >> 4) * 8)) * 2;

    for (; tile < ntiles; tile += gridDim.x) {
        __syncthreads();
        {   // convert + store x tile as fp16
            __half* sp = xs + lr * SXH;
#pragma unroll
            for (int i = 0; i < 8; i++) {
                float4 v = xr[i];
                __half2 h0 = __floats2half2_rn(v.x, v.y);
                __half2 h1 = __floats2half2_rn(v.z, v.w);
                uint2 pk = make_uint2(*(uint32_t*)&h0, *(uint32_t*)&h1);
                *(uint2*)(sp + (lq * 8 + i) * 4) = pk;
            }
        }
        __syncthreads();

        int next = tile + gridDim.x;
        if (next < ntiles) {
            int grow = next * GM + lr;
            const float* xp = x + (size_t)grow * C;
#pragma unroll
            for (int i = 0; i < 8; i++)
                xr[i] = (grow < n) ? *(const float4*)(xp + (lq * 8 + i) * 4)
                                   : make_float4(0.f, 0.f, 0.f, 0.f);
        }

        float acc[2][4][4];
#pragma unroll
        for (int ms = 0; ms < 2; ms++)
#pragma unroll
            for (int ns = 0; ns < 4; ns++)
#pragma unroll
                for (int j = 0; j < 4; j++) acc[ms][ns][j] = 0.f;

#pragma unroll
        for (int kk = 0; kk < 8; kk++) {
            const int kc = kk * 16;
            uint32_t a[2][4];
#pragma unroll
            for (int ms = 0; ms < 2; ms++)
                asm volatile("ldmatrix.sync.aligned.m8n8.x4.shared.b16 "
                             "{%0,%1,%2,%3}, [%4];"
                             : "=r"(a[ms][0]), "=r"(a[ms][1]),
                               "=r"(a[ms][2]), "=r"(a[ms][3])
                             : "r"(addrA[ms] + kc * 2));
#pragma unroll
            for (int ns = 0; ns < 4; ns++) {
                const __half* wp = ws + (wn * 32 + ns * 8 + g) * SWH + kc + 2 * t;
                uint32_t b0 = *(const uint32_t*)wp;        // k = kc+2t, +1
                uint32_t b1 = *(const uint32_t*)(wp + 8);  // k = kc+2t+8, +9
#pragma unroll
                for (int ms = 0; ms < 2; ms++) {
                    asm volatile(
                        "mma.sync.aligned.m16n8k16.row.col.f32.f16.f16.f32 "
                        "{%0,%1,%2,%3}, {%4,%5,%6,%7}, {%8,%9}, {%0,%1,%2,%3};"
                        : "+f"(acc[ms][ns][0]), "+f"(acc[ms][ns][1]),
                          "+f"(acc[ms][ns][2]), "+f"(acc[ms][ns][3])
                        : "r"(a[ms][0]), "r"(a[ms][1]),
                          "r"(a[ms][2]), "r"(a[ms][3]),
                          "r"(b0), "r"(b1));
                }
            }
        }

        // Epilogue: scale by dinv[row], store fp16 h'
        int row0 = tile * GM;
#pragma unroll
        for (int ms = 0; ms < 2; ms++) {
            int r = row0 + wm * 32 + ms * 16 + g;
            float s0 = (r < n)     ? g_dinv[r]     : 0.f;
            float s1 = (r + 8 < n) ? g_dinv[r + 8] : 0.f;
#pragma unroll
            for (int ns = 0; ns < 4; ns++) {
                int c = wn * 32 + ns * 8 + t * 2;
                if (r < n)
                    *(__half2*)(g_hh + (size_t)r * C + c) =
                        __floats2half2_rn(acc[ms][ns][0] * s0, acc[ms][ns][1] * s0);
                if (r + 8 < n)
                    *(__half2*)(g_hh + (size_t)(r + 8) * C + c) =
                        __floats2half2_rn(acc[ms][ns][2] * s1, acc[ms][ns][3] * s1);
            }
        }
    }
}

// ---------------------------------------------------------------------------
// Aggregate (R10 version): one warp per dst, 4-deep MLP fp16 gathers,
// fp32 accumulation. out = dinv[w]*(h'[w] + sum h'[src]) + b.
// ---------------------------------------------------------------------------
__device__ __forceinline__ void acc_row(float4& a, uint2 v) {
    float2 lo = __half22float2(*(__half2*)&v.x);
    float2 hi = __half22float2(*(__half2*)&v.y);
    a.x += lo.x; a.y += lo.y; a.z += hi.x; a.w += hi.y;
}

__global__ __launch_bounds__(256) void aggregate(const float* __restrict__ b,
                                                 float* __restrict__ out, int n) {
    int w    = (blockIdx.x * blockDim.x + threadIdx.x) >> 5;
    int lane = threadIdx.x & 31;
    if (w >= n) return;

    float di = g_dinv[w];
    int j  = g_rowptr[w];
    int j1 = g_rowptr[w + 1];
    if (lane == 0) g_deg[w] = 0;      // reset counts for next call

    const uint2* hbase = (const uint2*)g_hh;   // row r, lane l -> hbase[r*32+l]
    float4 a0 = make_float4(0.f, 0.f, 0.f, 0.f);
    float4 a1 = make_float4(0.f, 0.f, 0.f, 0.f);
    float4 a2 = make_float4(0.f, 0.f, 0.f, 0.f);
    float4 a3 = make_float4(0.f, 0.f, 0.f, 0.f);
    acc_row(a0, hbase[(size_t)w * 32 + lane]);   // self loop

    for (; j + 3 < j1; j += 4) {
        int sA = g_csrc[j], sB = g_csrc[j + 1], sC = g_csrc[j + 2], sD = g_csrc[j + 3];
        uint2 vA = hbase[(size_t)sA * 32 + lane];
        uint2 vB = hbase[(size_t)sB * 32 + lane];
        uint2 vC = hbase[(size_t)sC * 32 + lane];
        uint2 vD = hbase[(size_t)sD * 32 + lane];
        acc_row(a0, vA); acc_row(a1, vB); acc_row(a2, vC); acc_row(a3, vD);
    }
    for (; j < j1; j++)
        acc_row(a0, hbase[(size_t)g_csrc[j] * 32 + lane]);

    float4 bv = *(const float4*)(b + lane * 4);
    float4 o;
    o.x = fmaf(di, a0.x + a1.x + a2.x + a3.x, bv.x);
    o.y = fmaf(di, a0.y + a1.y + a2.y + a3.y, bv.y);
    o.z = fmaf(di, a0.z + a1.z + a2.z + a3.z, bv.z);
    o.w = fmaf(di, a0.w + a1.w + a2.w + a3.w, bv.w);
    *(float4*)(out + (size_t)w * C + lane * 4) = o;
}

// ---------------------------------------------------------------------------
extern "C" void kernel_launch(void* const* d_in, const int* in_sizes, int n_in,
                              void* d_out, int out_size) {
    const float* x  = (const float*)d_in[0];
    const int*   ei = (const int*)d_in[1];
    const float* W  = (const float*)d_in[2];
    const float* b  = (const float*)d_in[3];
    float* out = (float*)d_out;

    int n  = in_sizes[0] / C;
    int E  = in_sizes[1] / 2;
    int NB = (n + SCAN_B - 1) / SCAN_B;
    int EB = (E + 1023) / 1024;
    int ntiles = (n + GM - 1) / GM;
    int ggrid = ntiles < GEMM_GRID_MAX ? ntiles : GEMM_GRID_MAX;

    const int GEMM_SMEM = (GM * SXH + 128 * SWH) * (int)sizeof(__half);  // 52224 B
    cudaFuncSetAttribute(gemm_fp16, cudaFuncAttributeMaxDynamicSharedMemorySize,
                         GEMM_SMEM);

    count_deg<<<EB, 256>>>(ei, W, E, n, NB);
    scan_csr<<<NB, SCAN_B>>>(n);
    fill_csr<<<EB, 256>>>(ei, E);
    gemm_fp16<<<ggrid, 256, GEMM_SMEM>>>(x, n, ntiles);
    aggregate<<<(n * 32 + 255) / 256, 256>>>(b, out, n);
}